// round 6
// baseline (speedup 1.0000x reference)
#include <cuda_runtime.h>
#include <cuda_fp16.h>
#include <math.h>
#include <stdint.h>

// ---------------- problem dimensions ----------------
#define BDIM 1024
#define DIN  768
#define HID  256
#define DD   256
#define PTOT 21504

// ---------------- constants ----------------
#define CC        1.5f
#define SQRTC     1.22474487139158905f
#define INV_SQRTC 0.81649658092772603f
#define EPSF      1e-5f
#define INV_TEMP  14.285714285714286f
#define KLOG2     (-(INV_TEMP * INV_SQRTC * 0.69314718055994531f))

// ---------------- device scratch ----------------
__device__ __align__(16) float g_h1[BDIM * HID];
__device__ __align__(16) float g_h2[BDIM * HID];
__device__ __align__(16) float g_xx[BDIM];
__device__ __align__(16) float g_yy[PTOT];
__device__ __align__(16) __half g_ah[(size_t)BDIM * DD];    // f16(hyp)
__device__ __align__(16) __half g_bh[(size_t)PTOT * DD];    // f16(proto)

// ---------------- helpers ----------------
__device__ __forceinline__ uint32_t smem_u32(const void* p) {
    uint32_t a;
    asm("{ .reg .u64 t; cvta.to.shared.u64 t, %1; cvt.u32.u64 %0, t; }" : "=r"(a) : "l"(p));
    return a;
}
__device__ __forceinline__ void cp16(uint32_t s, const void* g) {
    asm volatile("cp.async.cg.shared.global [%0], [%1], 16;" :: "r"(s), "l"(g));
}
__device__ __forceinline__ void cp_commit() {
    asm volatile("cp.async.commit_group;" ::: "memory");
}
template<int N>
__device__ __forceinline__ void cp_wait() {
    asm volatile("cp.async.wait_group %0;" :: "n"(N) : "memory");
}
__device__ __forceinline__ void ldsm4(uint32_t* r, uint32_t addr) {
    asm volatile("ldmatrix.sync.aligned.m8n8.x4.shared.b16 {%0,%1,%2,%3}, [%4];"
                 : "=r"(r[0]), "=r"(r[1]), "=r"(r[2]), "=r"(r[3]) : "r"(addr));
}
__device__ __forceinline__ void mma16816(float* d, const uint32_t* a, uint32_t b0, uint32_t b1) {
    asm volatile("mma.sync.aligned.m16n8k16.row.col.f32.f16.f16.f32 "
                 "{%0,%1,%2,%3}, {%4,%5,%6,%7}, {%8,%9}, {%0,%1,%2,%3};"
                 : "+f"(d[0]), "+f"(d[1]), "+f"(d[2]), "+f"(d[3])
                 : "r"(a[0]), "r"(a[1]), "r"(a[2]), "r"(a[3]), "r"(b0), "r"(b1));
}
__device__ __forceinline__ float gelu_exact(float v) {
    return 0.5f * v * (1.0f + erff(v * 0.70710678118654752f));
}

// =====================================================================
// MLP GEMM (SIMT fp32, exact): tile 32x64, 128 threads -> 128 CTAs
// =====================================================================
template<int K, bool GELU>
__global__ __launch_bounds__(128)
void mlp_gemm(const float* __restrict__ A, const float* __restrict__ W,
              const float* __restrict__ bias, float* __restrict__ Cout)
{
    __shared__ float As[16][40];
    __shared__ float Bs[16][68];
    const int r0 = blockIdx.y * 32;
    const int n0 = blockIdx.x * 64;
    const int tid = threadIdx.x;
    const int rb = (tid >> 4) * 4;
    const int cb = (tid & 15) * 4;

    float acc[4][4] = {};

    for (int k0 = 0; k0 < K; k0 += 16) {
        {
            int row = tid >> 2;
            int kk  = (tid & 3) * 4;
            float4 v = *(const float4*)(A + (size_t)(r0 + row) * K + k0 + kk);
            As[kk + 0][row] = v.x; As[kk + 1][row] = v.y;
            As[kk + 2][row] = v.z; As[kk + 3][row] = v.w;
        }
        #pragma unroll
        for (int q = 0; q < 2; q++) {
            int idx = tid + q * 128;
            int k = idx >> 4;
            int n = (idx & 15) * 4;
            float4 v = *(const float4*)(W + (size_t)(k0 + k) * 256 + n0 + n);
            *(float4*)&Bs[k][n] = v;
        }
        __syncthreads();
        #pragma unroll
        for (int k = 0; k < 16; k++) {
            float a[4], bv[4];
            *(float4*)a  = *(const float4*)&As[k][rb];
            *(float4*)bv = *(const float4*)&Bs[k][cb];
            #pragma unroll
            for (int i = 0; i < 4; i++)
                #pragma unroll
                for (int j = 0; j < 4; j++)
                    acc[i][j] = fmaf(a[i], bv[j], acc[i][j]);
        }
        __syncthreads();
    }

    #pragma unroll
    for (int i = 0; i < 4; i++) {
        #pragma unroll
        for (int j = 0; j < 4; j++) {
            float v = acc[i][j] + bias[n0 + cb + j];
            if (GELU) v = gelu_exact(v);
            Cout[(size_t)(r0 + rb + i) * 256 + n0 + cb + j] = v;
        }
    }
}

// =====================================================================
// Fused layer-3 GEMM + expmap0: tile 16x256 (full width), 256 threads,
// 64 CTAs. Row norms are warp-local. Writes g_ah (f16) + g_xx directly.
// =====================================================================
__global__ __launch_bounds__(256)
void mlp3_expmap(const float* __restrict__ A, const float* __restrict__ W,
                 const float* __restrict__ bias)
{
    __shared__ float As[32][17];
    __shared__ float Bs[32][264];
    const int r0 = blockIdx.x * 16;
    const int tid  = threadIdx.x;
    const int wid  = tid >> 5;
    const int lane = tid & 31;
    const int cb = lane * 8;

    float acc[2][8] = {};

    for (int k0 = 0; k0 < 256; k0 += 32) {
        {   // A tile 16 rows x 32 k, transposed: 2 floats/thread
            int idx = tid * 2;
            int row = idx >> 5;
            int kk  = idx & 31;
            float2 v = *(const float2*)(A + (size_t)(r0 + row) * 256 + k0 + kk);
            As[kk][row] = v.x; As[kk + 1][row] = v.y;
        }
        #pragma unroll
        for (int q = 0; q < 8; q++) {   // W tile 32 k x 256 n
            int idx = tid + q * 256;
            int k = idx >> 6;
            int n = (idx & 63) * 4;
            float4 v = *(const float4*)(W + (size_t)(k0 + k) * 256 + n);
            *(float4*)&Bs[k][n] = v;
        }
        __syncthreads();
        #pragma unroll
        for (int k = 0; k < 32; k++) {
            float a0 = As[k][wid * 2];
            float a1 = As[k][wid * 2 + 1];
            float bv[8];
            *(float4*)&bv[0] = *(const float4*)&Bs[k][cb];
            *(float4*)&bv[4] = *(const float4*)&Bs[k][cb + 4];
            #pragma unroll
            for (int j = 0; j < 8; j++) {
                acc[0][j] = fmaf(a0, bv[j], acc[0][j]);
                acc[1][j] = fmaf(a1, bv[j], acc[1][j]);
            }
        }
        __syncthreads();
    }

    #pragma unroll
    for (int rr = 0; rr < 2; rr++) {
        const int row = r0 + wid * 2 + rr;
        float vv[8];
        float ss = 0.0f;
        #pragma unroll
        for (int j = 0; j < 8; j++) {
            vv[j] = acc[rr][j] + bias[cb + j];
            ss = fmaf(vv[j], vv[j], ss);
        }
        #pragma unroll
        for (int o = 16; o; o >>= 1) ss += __shfl_xor_sync(0xffffffffu, ss, o);
        float n = fmaxf(sqrtf(ss), EPSF);
        float scale = tanhf(SQRTC * n) / (SQRTC * n);
        if (lane == 0) g_xx[row] = scale * scale * ss;

        __half2 h[4];
        #pragma unroll
        for (int j = 0; j < 4; j++)
            h[j] = __floats2half2_rn(vv[j * 2] * scale, vv[j * 2 + 1] * scale);
        *(uint4*)(g_ah + (size_t)row * 256 + cb) = *(uint4*)h;
    }
}

// =====================================================================
// prototypes -> f16 + yy: 168 blocks, warp-per-row, 16 rows/warp
// =====================================================================
__global__ __launch_bounds__(256)
void proto_kernel(const float* __restrict__ proto)
{
    const int wid  = threadIdx.x >> 5;
    const int lane = threadIdx.x & 31;
    const int base = blockIdx.x * 128 + wid * 16;

    #pragma unroll 1
    for (int rr = 0; rr < 16; rr++) {
        const int p = base + rr;
        const float4* row = (const float4*)(proto + (size_t)p * 256);
        float4 a = row[lane];
        float4 b = row[lane + 32];
        float s = a.x * a.x + a.y * a.y + a.z * a.z + a.w * a.w
                + b.x * b.x + b.y * b.y + b.z * b.z + b.w * b.w;
        #pragma unroll
        for (int o = 16; o; o >>= 1) s += __shfl_xor_sync(0xffffffffu, s, o);
        if (lane == 0) g_yy[p] = s;

        __half2* dst = (__half2*)(g_bh + (size_t)p * 256);
        dst[lane * 2 + 0]      = __floats2half2_rn(a.x, a.y);
        dst[lane * 2 + 1]      = __floats2half2_rn(a.z, a.w);
        dst[64 + lane * 2 + 0] = __floats2half2_rn(b.x, b.y);
        dst[64 + lane * 2 + 1] = __floats2half2_rn(b.z, b.w);
    }
}

// =====================================================================
// Distance GEMM: 148 persistent CTAs (1/SM), CTA tile 256x128,
// 8 warps (4m x 2n), warp tile 64x64. A (256 x K=256) resident in SMEM,
// continuous 4-stage B pipeline across 4-5 column tiles.
// =====================================================================
#define ROWA 528                         // 512B + 16B pad
#define A_ROWS 256
#define A_BYTES (A_ROWS * ROWA)          // 135168
#define ROWB 80
#define B_ST (128 * ROWB)                // 10240
#define NST 4
#define SM_BYTES (A_BYTES + NST * B_ST)  // 176128
#define NCTA_PER_ROW 37
#define NCOLT 168                        // 21504 / 128

__global__ __launch_bounds__(256, 1)
void dist_mma(float* __restrict__ out)
{
    extern __shared__ __align__(128) char smem[];
    const uint32_t sb = smem_u32(smem);
    const int tid  = threadIdx.x;
    const int wid  = tid >> 5;
    const int lane = tid & 31;

    const int rg = blockIdx.x / NCTA_PER_ROW;    // 0..3
    const int j  = blockIdx.x % NCTA_PER_ROW;
    const int r0 = rg * 256;
    const int ntiles = (j < NCOLT - 4 * NCTA_PER_ROW) ? 5 : 4;   // j<20 -> 5
    const int n_iter = ntiles * 8;

    const int m0 = (wid >> 1) * 64;      // 4 m-warps
    const int n0 = (wid & 1) * 64;       // 2 n-warps

    // ---- load resident A tile (256 x 256 f16): 8192 x 16B chunks ----
    const __half* Ag = g_ah + (size_t)r0 * DD;
    #pragma unroll
    for (int q = 0; q < 32; q++) {
        int idx = tid + q * 256;
        int row = idx >> 5;
        int c   = idx & 31;
        cp16(sb + row * ROWA + c * 16, Ag + (size_t)row * DD + c * 8);
    }
    cp_commit();

    // ---- B stage loader: g -> (col tile g>>3, k-chunk g&7) ----
    auto loadB = [&](int g) {
        const int ctile = j + (g >> 3) * NCTA_PER_ROW;
        const __half* Bg = g_bh + (size_t)(ctile * 128) * DD;
        const uint32_t st = sb + A_BYTES + (g & (NST - 1)) * B_ST;
        const int k0 = (g & 7) * 32;
        const int i0 = tid * 2, i1 = tid * 2 + 1;
        cp16(st + (i0 >> 2) * ROWB + (i0 & 3) * 16, Bg + (size_t)(i0 >> 2) * DD + k0 + (i0 & 3) * 8);
        cp16(st + (i1 >> 2) * ROWB + (i1 & 3) * 16, Bg + (size_t)(i1 >> 2) * DD + k0 + (i1 & 3) * 8);
        cp_commit();
    };

    loadB(0); loadB(1); loadB(2);

    float acc[4][8][4] = {};
    const int qr = lane >> 2;
    const int qc = (lane & 3) * 2;

    #pragma unroll 1
    for (int g = 0; g < n_iter; g++) {
        cp_wait<2>();
        __syncthreads();

        const int i = g & 7;
        const uint32_t st = sb + A_BYTES + (g & (NST - 1)) * B_ST;
        const uint32_t abase = sb + (uint32_t)((m0 + (lane & 15)) * ROWA
                                               + i * 64 + (lane >> 4) * 16);
        const uint32_t bbase = st + (uint32_t)((n0 + (lane & 7) + ((lane >> 4) & 1) * 8) * ROWB
                                               + ((lane >> 3) & 1) * 16);
        #pragma unroll
        for (int ks = 0; ks < 2; ks++) {
            uint32_t ar[4][4], br[4][4];
            #pragma unroll
            for (int mi = 0; mi < 4; mi++)
                ldsm4(ar[mi], abase + mi * 16 * ROWA + ks * 32);
            #pragma unroll
            for (int nj = 0; nj < 4; nj++)
                ldsm4(br[nj], bbase + nj * 16 * ROWB + ks * 32);
            #pragma unroll
            for (int mi = 0; mi < 4; mi++)
                #pragma unroll
                for (int nj = 0; nj < 4; nj++) {
                    mma16816(acc[mi][nj * 2],     ar[mi], br[nj][0], br[nj][1]);
                    mma16816(acc[mi][nj * 2 + 1], ar[mi], br[nj][2], br[nj][3]);
                }
        }

        if (g + 3 < n_iter) loadB(g + 3);
        else                cp_commit();          // keep wait-count invariant

        if (i == 7) {
            // ---------------- fused Poincare epilogue for this col tile ----------------
            const int c0 = ((g >> 3) * NCTA_PER_ROW + j) * 128;
            size_t lvl_base; int lvl_stride, lvl_start;
            if (c0 < 1024)      { lvl_base = 0;                                         lvl_stride = 1024;  lvl_start = 0;    }
            else if (c0 < 5120) { lvl_base = (size_t)1024 * 1024;                       lvl_stride = 4096;  lvl_start = 1024; }
            else                { lvl_base = (size_t)1024 * 1024 + (size_t)4096 * 1024; lvl_stride = 16384; lvl_start = 5120; }

            #pragma unroll
            for (int mi = 0; mi < 4; mi++) {
                const int ra = r0 + m0 + mi * 16 + qr;
                const float xx0 = g_xx[ra];
                const float xx1 = g_xx[ra + 8];
                const float bb0 = 1.0f - CC * xx0;
                const float bb1 = 1.0f - CC * xx1;
                float* orow0 = out + lvl_base + (size_t)ra * lvl_stride + (c0 - lvl_start);
                float* orow1 = orow0 + (size_t)8 * lvl_stride;

                #pragma unroll
                for (int nj = 0; nj < 8; nj++) {
                    const int col = n0 + nj * 8 + qc;
                    const float2 yyp = *(const float2*)(g_yy + c0 + col);
                    float* a4 = acc[mi][nj];

                    float r[4];
                    #pragma unroll
                    for (int q = 0; q < 4; q++) {
                        const float xy = a4[q];
                        const float xx = (q < 2) ? xx0 : xx1;
                        const float bb = (q < 2) ? bb0 : bb1;
                        const float yv = (q & 1) ? yyp.y : yyp.x;
                        float w     = fmaf(-2.0f * CC, xy, 1.0f);
                        float a     = fmaf(CC, yv, w);
                        float denom = fmaf(CC * CC * xx, yv, w);
                        float num2  = a * a * xx + bb * bb * yv - 2.0f * a * bb * xy;
                        float s  = SQRTC * sqrtf(fmaxf(num2, 0.0f));
                        float td = fmaxf(fabsf(denom), 1e-30f);
                        s = fminf(s, (1.0f - EPSF) * td);
                        float ratio = __fdividef(td + s, td - s);
                        r[q] = KLOG2 * __log2f(ratio);
                        a4[q] = 0.0f;                     // reset for next tile
                    }
                    *(float2*)(orow0 + col) = make_float2(r[0], r[1]);
                    *(float2*)(orow1 + col) = make_float2(r[2], r[3]);
                }
            }
        }
    }
}

// =====================================================================
// launch
// =====================================================================
extern "C" void kernel_launch(void* const* d_in, const int* in_sizes, int n_in,
                              void* d_out, int out_size)
{
    const float* x     = (const float*)d_in[0];
    const float* W1    = (const float*)d_in[1];
    const float* b1    = (const float*)d_in[2];
    const float* W2    = (const float*)d_in[3];
    const float* b2    = (const float*)d_in[4];
    const float* W3    = (const float*)d_in[5];
    const float* b3    = (const float*)d_in[6];
    const float* proto = (const float*)d_in[7];
    float* out = (float*)d_out;

    float *p_h1, *p_h2;
    cudaGetSymbolAddress((void**)&p_h1, g_h1);
    cudaGetSymbolAddress((void**)&p_h2, g_h2);

    cudaFuncSetAttribute(dist_mma, cudaFuncAttributeMaxDynamicSharedMemorySize, SM_BYTES);

    mlp_gemm<768, true ><<<dim3(4, 32), 128>>>(x,    W1, b1, p_h1);
    mlp_gemm<256, true ><<<dim3(4, 32), 128>>>(p_h1, W2, b2, p_h2);
    mlp3_expmap<<<64, 256>>>(p_h2, W3, b3);
    proto_kernel<<<NCOLT, 256>>>(proto);
    dist_mma<<<4 * NCTA_PER_ROW, 256, SM_BYTES>>>(out);
}

// round 7
// speedup vs baseline: 1.2406x; 1.2406x over previous
#include <cuda_runtime.h>
#include <cuda_fp16.h>
#include <math.h>
#include <stdint.h>

// ---------------- problem dimensions ----------------
#define BDIM 1024
#define DIN  768
#define HID  256
#define DD   256
#define PTOT 21504

// ---------------- constants ----------------
#define CC        1.5f
#define SQRTC     1.22474487139158905f
#define INV_SQRTC 0.81649658092772603f
#define EPSF      1e-5f
#define INV_TEMP  14.285714285714286f
#define KLOG2     (-(INV_TEMP * INV_SQRTC * 0.69314718055994531f))

// ---------------- device scratch ----------------
__device__ __align__(16) float g_h1[BDIM * HID];
__device__ __align__(16) float g_h2[BDIM * HID];
__device__ __align__(16) float g_xx[BDIM];
__device__ __align__(16) float g_yy[PTOT];
__device__ __align__(16) __half g_ah[(size_t)BDIM * DD];    // f16(hyp)
__device__ __align__(16) __half g_bh[(size_t)PTOT * DD];    // f16(proto)

// ---------------- helpers ----------------
__device__ __forceinline__ uint32_t smem_u32(const void* p) {
    uint32_t a;
    asm("{ .reg .u64 t; cvta.to.shared.u64 t, %1; cvt.u32.u64 %0, t; }" : "=r"(a) : "l"(p));
    return a;
}
__device__ __forceinline__ void cp16(uint32_t s, const void* g) {
    asm volatile("cp.async.cg.shared.global [%0], [%1], 16;" :: "r"(s), "l"(g));
}
__device__ __forceinline__ void cp_commit() {
    asm volatile("cp.async.commit_group;" ::: "memory");
}
template<int N>
__device__ __forceinline__ void cp_wait() {
    asm volatile("cp.async.wait_group %0;" :: "n"(N) : "memory");
}
__device__ __forceinline__ void ldsm4(uint32_t* r, uint32_t addr) {
    asm volatile("ldmatrix.sync.aligned.m8n8.x4.shared.b16 {%0,%1,%2,%3}, [%4];"
                 : "=r"(r[0]), "=r"(r[1]), "=r"(r[2]), "=r"(r[3]) : "r"(addr));
}
__device__ __forceinline__ void mma16816(float* d, const uint32_t* a, uint32_t b0, uint32_t b1) {
    asm volatile("mma.sync.aligned.m16n8k16.row.col.f32.f16.f16.f32 "
                 "{%0,%1,%2,%3}, {%4,%5,%6,%7}, {%8,%9}, {%0,%1,%2,%3};"
                 : "+f"(d[0]), "+f"(d[1]), "+f"(d[2]), "+f"(d[3])
                 : "r"(a[0]), "r"(a[1]), "r"(a[2]), "r"(a[3]), "r"(b0), "r"(b1));
}
__device__ __forceinline__ float gelu_exact(float v) {
    return 0.5f * v * (1.0f + erff(v * 0.70710678118654752f));
}

// =====================================================================
// MLP GEMM (SIMT fp32, exact): tile 32x64, 128 threads -> 128 CTAs
// =====================================================================
template<int K, bool GELU>
__global__ __launch_bounds__(128)
void mlp_gemm(const float* __restrict__ A, const float* __restrict__ W,
              const float* __restrict__ bias, float* __restrict__ Cout)
{
    __shared__ float As[16][40];
    __shared__ float Bs[16][68];
    const int r0 = blockIdx.y * 32;
    const int n0 = blockIdx.x * 64;
    const int tid = threadIdx.x;
    const int rb = (tid >> 4) * 4;
    const int cb = (tid & 15) * 4;

    float acc[4][4] = {};

    for (int k0 = 0; k0 < K; k0 += 16) {
        {
            int row = tid >> 2;
            int kk  = (tid & 3) * 4;
            float4 v = *(const float4*)(A + (size_t)(r0 + row) * K + k0 + kk);
            As[kk + 0][row] = v.x; As[kk + 1][row] = v.y;
            As[kk + 2][row] = v.z; As[kk + 3][row] = v.w;
        }
        #pragma unroll
        for (int q = 0; q < 2; q++) {
            int idx = tid + q * 128;
            int k = idx >> 4;
            int n = (idx & 15) * 4;
            float4 v = *(const float4*)(W + (size_t)(k0 + k) * 256 + n0 + n);
            *(float4*)&Bs[k][n] = v;
        }
        __syncthreads();
        #pragma unroll
        for (int k = 0; k < 16; k++) {
            float a[4], bv[4];
            *(float4*)a  = *(const float4*)&As[k][rb];
            *(float4*)bv = *(const float4*)&Bs[k][cb];
            #pragma unroll
            for (int i = 0; i < 4; i++)
                #pragma unroll
                for (int j = 0; j < 4; j++)
                    acc[i][j] = fmaf(a[i], bv[j], acc[i][j]);
        }
        __syncthreads();
    }

    #pragma unroll
    for (int i = 0; i < 4; i++) {
        #pragma unroll
        for (int j = 0; j < 4; j++) {
            float v = acc[i][j] + bias[n0 + cb + j];
            if (GELU) v = gelu_exact(v);
            Cout[(size_t)(r0 + rb + i) * 256 + n0 + cb + j] = v;
        }
    }
}

// =====================================================================
// Fused layer-3 GEMM + expmap0: tile 16x256 (full width), 256 threads,
// 64 CTAs. Row norms are warp-local. Writes g_ah (f16) + g_xx directly.
// =====================================================================
__global__ __launch_bounds__(256)
void mlp3_expmap(const float* __restrict__ A, const float* __restrict__ W,
                 const float* __restrict__ bias)
{
    __shared__ float As[32][17];
    __shared__ float Bs[32][264];
    const int r0 = blockIdx.x * 16;
    const int tid  = threadIdx.x;
    const int wid  = tid >> 5;
    const int lane = tid & 31;
    const int cb = lane * 8;

    float acc[2][8] = {};

    for (int k0 = 0; k0 < 256; k0 += 32) {
        {   // A tile 16 rows x 32 k, transposed: 2 floats/thread
            int idx = tid * 2;
            int row = idx >> 5;
            int kk  = idx & 31;
            float2 v = *(const float2*)(A + (size_t)(r0 + row) * 256 + k0 + kk);
            As[kk][row] = v.x; As[kk + 1][row] = v.y;
        }
        #pragma unroll
        for (int q = 0; q < 8; q++) {   // W tile 32 k x 256 n
            int idx = tid + q * 256;
            int k = idx >> 6;
            int n = (idx & 63) * 4;
            float4 v = *(const float4*)(W + (size_t)(k0 + k) * 256 + n);
            *(float4*)&Bs[k][n] = v;
        }
        __syncthreads();
        #pragma unroll
        for (int k = 0; k < 32; k++) {
            float a0 = As[k][wid * 2];
            float a1 = As[k][wid * 2 + 1];
            float bv[8];
            *(float4*)&bv[0] = *(const float4*)&Bs[k][cb];
            *(float4*)&bv[4] = *(const float4*)&Bs[k][cb + 4];
            #pragma unroll
            for (int j = 0; j < 8; j++) {
                acc[0][j] = fmaf(a0, bv[j], acc[0][j]);
                acc[1][j] = fmaf(a1, bv[j], acc[1][j]);
            }
        }
        __syncthreads();
    }

    #pragma unroll
    for (int rr = 0; rr < 2; rr++) {
        const int row = r0 + wid * 2 + rr;
        float vv[8];
        float ss = 0.0f;
        #pragma unroll
        for (int j = 0; j < 8; j++) {
            vv[j] = acc[rr][j] + bias[cb + j];
            ss = fmaf(vv[j], vv[j], ss);
        }
        #pragma unroll
        for (int o = 16; o; o >>= 1) ss += __shfl_xor_sync(0xffffffffu, ss, o);
        float n = fmaxf(sqrtf(ss), EPSF);
        float scale = tanhf(SQRTC * n) / (SQRTC * n);
        if (lane == 0) g_xx[row] = scale * scale * ss;

        __half2 h[4];
        #pragma unroll
        for (int j = 0; j < 4; j++)
            h[j] = __floats2half2_rn(vv[j * 2] * scale, vv[j * 2 + 1] * scale);
        *(uint4*)(g_ah + (size_t)row * 256 + cb) = *(uint4*)h;
    }
}

// =====================================================================
// prototypes -> f16 + yy: 2688 blocks, warp-per-row, no row loop
// =====================================================================
__global__ __launch_bounds__(256)
void proto_kernel(const float* __restrict__ proto)
{
    const int wid  = threadIdx.x >> 5;
    const int lane = threadIdx.x & 31;
    const int p = blockIdx.x * 8 + wid;

    const float4* row = (const float4*)(proto + (size_t)p * 256);
    float4 a = row[lane];
    float4 b = row[lane + 32];
    float s = a.x * a.x + a.y * a.y + a.z * a.z + a.w * a.w
            + b.x * b.x + b.y * b.y + b.z * b.z + b.w * b.w;
    #pragma unroll
    for (int o = 16; o; o >>= 1) s += __shfl_xor_sync(0xffffffffu, s, o);
    if (lane == 0) g_yy[p] = s;

    __half2 h0[2] = { __floats2half2_rn(a.x, a.y), __floats2half2_rn(a.z, a.w) };
    __half2 h1[2] = { __floats2half2_rn(b.x, b.y), __floats2half2_rn(b.z, b.w) };
    __half2* dst = (__half2*)(g_bh + (size_t)p * 256);
    *(uint2*)(dst + lane * 2)      = *(uint2*)h0;
    *(uint2*)(dst + 64 + lane * 2) = *(uint2*)h1;
}

// =====================================================================
// Distance GEMM (R5 config — known good): persistent CTAs, resident A
// (128 rows, full K), continuous 4-stage B pipeline across 4-5 column
// tiles. 296 CTAs (2/SM). 8 warps (2m x 4n), warp tile 64x32.
// =====================================================================
#define ROWA 528                       // 512B data + 16B pad
#define A_BYTES (128 * ROWA)           // 67584
#define ROWB 80
#define B_ST (128 * ROWB)              // 10240
#define NST 4
#define SM_BYTES (A_BYTES + NST * B_ST)  // 108544
#define NCTA_PER_ROW 37
#define NCOLT 168                      // 21504 / 128

__global__ __launch_bounds__(256, 2)
void dist_mma(float* __restrict__ out)
{
    extern __shared__ __align__(128) char smem[];
    const uint32_t sb = smem_u32(smem);
    const int tid  = threadIdx.x;
    const int wid  = tid >> 5;
    const int lane = tid & 31;

    const int rg = blockIdx.x / NCTA_PER_ROW;    // row group 0..7
    const int j  = blockIdx.x % NCTA_PER_ROW;    // col stride offset
    const int r0 = rg * 128;
    const int ntiles = (j < NCOLT - 4 * NCTA_PER_ROW) ? 5 : 4;   // j<20 -> 5
    const int n_iter = ntiles * 8;

    const int m0 = (wid >> 2) * 64;
    const int n0 = (wid & 3) * 32;

    // ---- load A tile (128 x 256 f16) once: 4096 x 16B chunks ----
    const __half* Ag = g_ah + (size_t)r0 * DD;
    #pragma unroll
    for (int q = 0; q < 16; q++) {
        int idx = tid + q * 256;
        int row = idx >> 5;
        int c   = idx & 31;
        cp16(sb + row * ROWA + c * 16, Ag + (size_t)row * DD + c * 8);
    }
    cp_commit();

    // ---- B stage loader: flat iteration g -> (tile ct = g>>3, kchunk i = g&7) ----
    auto loadB = [&](int g) {
        const int ctile = j + (g >> 3) * NCTA_PER_ROW;
        const __half* Bg = g_bh + (size_t)(ctile * 128) * DD;
        const uint32_t st = sb + A_BYTES + (g & (NST - 1)) * B_ST;
        const int k0 = (g & 7) * 32;
        const int i0 = tid * 2, i1 = tid * 2 + 1;
        cp16(st + (i0 >> 2) * ROWB + (i0 & 3) * 16, Bg + (size_t)(i0 >> 2) * DD + k0 + (i0 & 3) * 8);
        cp16(st + (i1 >> 2) * ROWB + (i1 & 3) * 16, Bg + (size_t)(i1 >> 2) * DD + k0 + (i1 & 3) * 8);
        cp_commit();
    };

    loadB(0); loadB(1); loadB(2);

    float acc[4][4][4] = {};
    const int qr = lane >> 2;
    const int qc = (lane & 3) * 2;

    #pragma unroll 1
    for (int g = 0; g < n_iter; g++) {
        cp_wait<2>();
        __syncthreads();

        const int i = g & 7;
        const uint32_t st = sb + A_BYTES + (g & (NST - 1)) * B_ST;
        const uint32_t abase = sb + (uint32_t)((m0 + (lane & 15)) * ROWA
                                               + i * 64 + (lane >> 4) * 16);
        const uint32_t bbase = st + (uint32_t)((n0 + (lane & 7) + ((lane >> 4) & 1) * 8) * ROWB
                                               + ((lane >> 3) & 1) * 16);
        #pragma unroll
        for (int ks = 0; ks < 2; ks++) {
            uint32_t br[2][4];
            #pragma unroll
            for (int jj = 0; jj < 2; jj++)
                ldsm4(br[jj], bbase + jj * 16 * ROWB + ks * 32);
            #pragma unroll
            for (int mi = 0; mi < 4; mi++) {
                uint32_t ar[4];
                ldsm4(ar, abase + mi * 16 * ROWA + ks * 32);
                mma16816(acc[mi][0], ar, br[0][0], br[0][1]);
                mma16816(acc[mi][1], ar, br[0][2], br[0][3]);
                mma16816(acc[mi][2], ar, br[1][0], br[1][1]);
                mma16816(acc[mi][3], ar, br[1][2], br[1][3]);
            }
        }

        if (g + 3 < n_iter) loadB(g + 3);
        else                cp_commit();          // keep wait-count invariant

        if (i == 7) {
            // ---------------- fused Poincare epilogue for this col tile ----------------
            const int c0 = ((g >> 3) * NCTA_PER_ROW + j) * 128;
            size_t lvl_base; int lvl_stride, lvl_start;
            if (c0 < 1024)      { lvl_base = 0;                                         lvl_stride = 1024;  lvl_start = 0;    }
            else if (c0 < 5120) { lvl_base = (size_t)1024 * 1024;                       lvl_stride = 4096;  lvl_start = 1024; }
            else                { lvl_base = (size_t)1024 * 1024 + (size_t)4096 * 1024; lvl_stride = 16384; lvl_start = 5120; }

            #pragma unroll
            for (int mi = 0; mi < 4; mi++) {
                const int ra = r0 + m0 + mi * 16 + qr;
                const float xx0 = g_xx[ra];
                const float xx1 = g_xx[ra + 8];
                const float bb0 = 1.0f - CC * xx0;
                const float bb1 = 1.0f - CC * xx1;
                float* orow0 = out + lvl_base + (size_t)ra * lvl_stride + (c0 - lvl_start);
                float* orow1 = orow0 + (size_t)8 * lvl_stride;

                #pragma unroll
                for (int ni = 0; ni < 4; ni++) {
                    const int col = n0 + ni * 8 + qc;
                    const float2 yyp = *(const float2*)(g_yy + c0 + col);
                    float* a4 = acc[mi][ni];

                    float r[4];
                    #pragma unroll
                    for (int q = 0; q < 4; q++) {
                        const float xy = a4[q];
                        const float xx = (q < 2) ? xx0 : xx1;
                        const float bb = (q < 2) ? bb0 : bb1;
                        const float yv = (q & 1) ? yyp.y : yyp.x;
                        float w     = fmaf(-2.0f * CC, xy, 1.0f);
                        float a     = fmaf(CC, yv, w);
                        float denom = fmaf(CC * CC * xx, yv, w);
                        float num2  = a * a * xx + bb * bb * yv - 2.0f * a * bb * xy;
                        float s  = SQRTC * sqrtf(fmaxf(num2, 0.0f));
                        float td = fmaxf(fabsf(denom), 1e-30f);
                        s = fminf(s, (1.0f - EPSF) * td);
                        float ratio = __fdividef(td + s, td - s);
                        r[q] = KLOG2 * __log2f(ratio);
                        a4[q] = 0.0f;                     // reset acc for next tile
                    }
                    *(float2*)(orow0 + col) = make_float2(r[0], r[1]);
                    *(float2*)(orow1 + col) = make_float2(r[2], r[3]);
                }
            }
        }
    }
}

// =====================================================================
// launch
// =====================================================================
extern "C" void kernel_launch(void* const* d_in, const int* in_sizes, int n_in,
                              void* d_out, int out_size)
{
    const float* x     = (const float*)d_in[0];
    const float* W1    = (const float*)d_in[1];
    const float* b1    = (const float*)d_in[2];
    const float* W2    = (const float*)d_in[3];
    const float* b2    = (const float*)d_in[4];
    const float* W3    = (const float*)d_in[5];
    const float* b3    = (const float*)d_in[6];
    const float* proto = (const float*)d_in[7];
    float* out = (float*)d_out;

    float *p_h1, *p_h2;
    cudaGetSymbolAddress((void**)&p_h1, g_h1);
    cudaGetSymbolAddress((void**)&p_h2, g_h2);

    cudaFuncSetAttribute(dist_mma, cudaFuncAttributeMaxDynamicSharedMemorySize, SM_BYTES);

    proto_kernel<<<PTOT / 8, 256>>>(proto);
    mlp_gemm<768, true ><<<dim3(4, 32), 128>>>(x,    W1, b1, p_h1);
    mlp_gemm<256, true ><<<dim3(4, 32), 128>>>(p_h1, W2, b2, p_h2);
    mlp3_expmap<<<64, 256>>>(p_h2, W3, b3);
    dist_mma<<<8 * NCTA_PER_ROW, 256, SM_BYTES>>>(out);
}

// round 8
// speedup vs baseline: 1.3339x; 1.0752x over previous
#include <cuda_runtime.h>
#include <cuda_fp16.h>
#include <math.h>
#include <stdint.h>

// ---------------- problem dimensions ----------------
#define BDIM 1024
#define DIN  768
#define HID  256
#define DD   256
#define PTOT 21504

// ---------------- constants ----------------
#define CC        1.5f
#define SQRTC     1.22474487139158905f
#define INV_SQRTC 0.81649658092772603f
#define EPSF      1e-5f
#define INV_TEMP  14.285714285714286f
#define KLOG2     (-(INV_TEMP * INV_SQRTC * 0.69314718055994531f))

// ---------------- device scratch ----------------
__device__ __align__(16) float g_h1[BDIM * HID];
__device__ __align__(16) float g_h2[BDIM * HID];
__device__ __align__(16) float g_f [BDIM * DD];
__device__ __align__(16) float g_xx[BDIM];
__device__ __align__(16) float g_yy[PTOT];
__device__ __align__(16) __half g_ah[(size_t)BDIM * DD];    // f16(hyp)
__device__ __align__(16) __half g_bh[(size_t)PTOT * DD];    // f16(proto)

// ---------------- helpers ----------------
__device__ __forceinline__ uint32_t smem_u32(const void* p) {
    uint32_t a;
    asm("{ .reg .u64 t; cvta.to.shared.u64 t, %1; cvt.u32.u64 %0, t; }" : "=r"(a) : "l"(p));
    return a;
}
__device__ __forceinline__ void cp16(uint32_t s, const void* g) {
    asm volatile("cp.async.cg.shared.global [%0], [%1], 16;" :: "r"(s), "l"(g));
}
__device__ __forceinline__ void cp_commit() {
    asm volatile("cp.async.commit_group;" ::: "memory");
}
template<int N>
__device__ __forceinline__ void cp_wait() {
    asm volatile("cp.async.wait_group %0;" :: "n"(N) : "memory");
}
__device__ __forceinline__ void ldsm4(uint32_t* r, uint32_t addr) {
    asm volatile("ldmatrix.sync.aligned.m8n8.x4.shared.b16 {%0,%1,%2,%3}, [%4];"
                 : "=r"(r[0]), "=r"(r[1]), "=r"(r[2]), "=r"(r[3]) : "r"(addr));
}
__device__ __forceinline__ void mma16816(float* d, const uint32_t* a, uint32_t b0, uint32_t b1) {
    asm volatile("mma.sync.aligned.m16n8k16.row.col.f32.f16.f16.f32 "
                 "{%0,%1,%2,%3}, {%4,%5,%6,%7}, {%8,%9}, {%0,%1,%2,%3};"
                 : "+f"(d[0]), "+f"(d[1]), "+f"(d[2]), "+f"(d[3])
                 : "r"(a[0]), "r"(a[1]), "r"(a[2]), "r"(a[3]), "r"(b0), "r"(b1));
}
__device__ __forceinline__ float gelu_exact(float v) {
    return 0.5f * v * (1.0f + erff(v * 0.70710678118654752f));
}

// =====================================================================
// MLP GEMM (SIMT fp32, exact): tile 32x64, 128 threads -> 128 CTAs
// =====================================================================
template<int K, bool GELU>
__global__ __launch_bounds__(128)
void mlp_gemm(const float* __restrict__ A, const float* __restrict__ W,
              const float* __restrict__ bias, float* __restrict__ Cout)
{
    __shared__ float As[16][40];
    __shared__ float Bs[16][68];
    const int r0 = blockIdx.y * 32;
    const int n0 = blockIdx.x * 64;
    const int tid = threadIdx.x;
    const int rb = (tid >> 4) * 4;
    const int cb = (tid & 15) * 4;

    float acc[4][4] = {};

    for (int k0 = 0; k0 < K; k0 += 16) {
        {
            int row = tid >> 2;
            int kk  = (tid & 3) * 4;
            float4 v = *(const float4*)(A + (size_t)(r0 + row) * K + k0 + kk);
            As[kk + 0][row] = v.x; As[kk + 1][row] = v.y;
            As[kk + 2][row] = v.z; As[kk + 3][row] = v.w;
        }
        #pragma unroll
        for (int q = 0; q < 2; q++) {
            int idx = tid + q * 128;
            int k = idx >> 4;
            int n = (idx & 15) * 4;
            float4 v = *(const float4*)(W + (size_t)(k0 + k) * 256 + n0 + n);
            *(float4*)&Bs[k][n] = v;
        }
        __syncthreads();
        #pragma unroll
        for (int k = 0; k < 16; k++) {
            float a[4], bv[4];
            *(float4*)a  = *(const float4*)&As[k][rb];
            *(float4*)bv = *(const float4*)&Bs[k][cb];
            #pragma unroll
            for (int i = 0; i < 4; i++)
                #pragma unroll
                for (int j = 0; j < 4; j++)
                    acc[i][j] = fmaf(a[i], bv[j], acc[i][j]);
        }
        __syncthreads();
    }

    #pragma unroll
    for (int i = 0; i < 4; i++) {
        #pragma unroll
        for (int j = 0; j < 4; j++) {
            float v = acc[i][j] + bias[n0 + cb + j];
            if (GELU) v = gelu_exact(v);
            Cout[(size_t)(r0 + rb + i) * 256 + n0 + cb + j] = v;
        }
    }
}

// =====================================================================
// expmap0 -> f16 hyp + xx = ||hyp||^2  (R5 version, ~5us)
// =====================================================================
__global__ __launch_bounds__(256)
void expmap_kernel()
{
    const int b = blockIdx.x;
    const int t = threadIdx.x;
    float v = g_f[(size_t)b * DD + t];
    float s = v * v;
    #pragma unroll
    for (int o = 16; o; o >>= 1) s += __shfl_xor_sync(0xffffffffu, s, o);

    __shared__ float ws[8];
    __shared__ float s_scale;
    if ((t & 31) == 0) ws[t >> 5] = s;
    __syncthreads();
    if (t < 8) {
        float x = ws[t];
        #pragma unroll
        for (int o = 4; o; o >>= 1) x += __shfl_xor_sync(0x000000ffu, x, o);
        if (t == 0) {
            float ss = x;
            float n = fmaxf(sqrtf(ss), EPSF);
            float scale = tanhf(SQRTC * n) / (SQRTC * n);
            s_scale = scale;
            g_xx[b] = scale * scale * ss;
        }
    }
    __syncthreads();
    g_ah[(size_t)b * DD + t] = __float2half(v * s_scale);
}

// =====================================================================
// prototypes -> f16 + yy: 2688 blocks, warp-per-row (R7 verified win)
// =====================================================================
__global__ __launch_bounds__(256)
void proto_kernel(const float* __restrict__ proto)
{
    const int wid  = threadIdx.x >> 5;
    const int lane = threadIdx.x & 31;
    const int p = blockIdx.x * 8 + wid;

    const float4* row = (const float4*)(proto + (size_t)p * 256);
    float4 a = row[lane];
    float4 b = row[lane + 32];
    float s = a.x * a.x + a.y * a.y + a.z * a.z + a.w * a.w
            + b.x * b.x + b.y * b.y + b.z * b.z + b.w * b.w;
    #pragma unroll
    for (int o = 16; o; o >>= 1) s += __shfl_xor_sync(0xffffffffu, s, o);
    if (lane == 0) g_yy[p] = s;

    __half2 h0[2] = { __floats2half2_rn(a.x, a.y), __floats2half2_rn(a.z, a.w) };
    __half2 h1[2] = { __floats2half2_rn(b.x, b.y), __floats2half2_rn(b.z, b.w) };
    __half2* dst = (__half2*)(g_bh + (size_t)p * 256);
    *(uint2*)(dst + lane * 2)      = *(uint2*)h0;
    *(uint2*)(dst + 64 + lane * 2) = *(uint2*)h1;
}

// =====================================================================
// Distance GEMM (R5 config — known good): persistent CTAs, resident A
// (128 rows, full K), continuous 4-stage B pipeline across 4-5 column
// tiles. 296 CTAs (2/SM). 8 warps (2m x 4n), warp tile 64x32.
// =====================================================================
#define ROWA 528                       // 512B data + 16B pad
#define A_BYTES (128 * ROWA)           // 67584
#define ROWB 80
#define B_ST (128 * ROWB)              // 10240
#define NST 4
#define SM_BYTES (A_BYTES + NST * B_ST)  // 108544
#define NCTA_PER_ROW 37
#define NCOLT 168                      // 21504 / 128

__global__ __launch_bounds__(256, 2)
void dist_mma(float* __restrict__ out)
{
    extern __shared__ __align__(128) char smem[];
    const uint32_t sb = smem_u32(smem);
    const int tid  = threadIdx.x;
    const int wid  = tid >> 5;
    const int lane = tid & 31;

    const int rg = blockIdx.x / NCTA_PER_ROW;    // row group 0..7
    const int j  = blockIdx.x % NCTA_PER_ROW;    // col stride offset
    const int r0 = rg * 128;
    const int ntiles = (j < NCOLT - 4 * NCTA_PER_ROW) ? 5 : 4;   // j<20 -> 5
    const int n_iter = ntiles * 8;

    const int m0 = (wid >> 2) * 64;
    const int n0 = (wid & 3) * 32;

    // ---- load A tile (128 x 256 f16) once: 4096 x 16B chunks ----
    const __half* Ag = g_ah + (size_t)r0 * DD;
    #pragma unroll
    for (int q = 0; q < 16; q++) {
        int idx = tid + q * 256;
        int row = idx >> 5;
        int c   = idx & 31;
        cp16(sb + row * ROWA + c * 16, Ag + (size_t)row * DD + c * 8);
    }
    cp_commit();

    // ---- B stage loader: flat iteration g -> (tile ct = g>>3, kchunk i = g&7) ----
    auto loadB = [&](int g) {
        const int ctile = j + (g >> 3) * NCTA_PER_ROW;
        const __half* Bg = g_bh + (size_t)(ctile * 128) * DD;
        const uint32_t st = sb + A_BYTES + (g & (NST - 1)) * B_ST;
        const int k0 = (g & 7) * 32;
        const int i0 = tid * 2, i1 = tid * 2 + 1;
        cp16(st + (i0 >> 2) * ROWB + (i0 & 3) * 16, Bg + (size_t)(i0 >> 2) * DD + k0 + (i0 & 3) * 8);
        cp16(st + (i1 >> 2) * ROWB + (i1 & 3) * 16, Bg + (size_t)(i1 >> 2) * DD + k0 + (i1 & 3) * 8);
        cp_commit();
    };

    loadB(0); loadB(1); loadB(2);

    float acc[4][4][4] = {};
    const int qr = lane >> 2;
    const int qc = (lane & 3) * 2;

    #pragma unroll 1
    for (int g = 0; g < n_iter; g++) {
        cp_wait<2>();
        __syncthreads();

        const int i = g & 7;
        const uint32_t st = sb + A_BYTES + (g & (NST - 1)) * B_ST;
        const uint32_t abase = sb + (uint32_t)((m0 + (lane & 15)) * ROWA
                                               + i * 64 + (lane >> 4) * 16);
        const uint32_t bbase = st + (uint32_t)((n0 + (lane & 7) + ((lane >> 4) & 1) * 8) * ROWB
                                               + ((lane >> 3) & 1) * 16);
        #pragma unroll
        for (int ks = 0; ks < 2; ks++) {
            uint32_t br[2][4];
            #pragma unroll
            for (int jj = 0; jj < 2; jj++)
                ldsm4(br[jj], bbase + jj * 16 * ROWB + ks * 32);
            #pragma unroll
            for (int mi = 0; mi < 4; mi++) {
                uint32_t ar[4];
                ldsm4(ar, abase + mi * 16 * ROWA + ks * 32);
                mma16816(acc[mi][0], ar, br[0][0], br[0][1]);
                mma16816(acc[mi][1], ar, br[0][2], br[0][3]);
                mma16816(acc[mi][2], ar, br[1][0], br[1][1]);
                mma16816(acc[mi][3], ar, br[1][2], br[1][3]);
            }
        }

        if (g + 3 < n_iter) loadB(g + 3);
        else                cp_commit();          // keep wait-count invariant

        if (i == 7) {
            // ---------------- fused Poincare epilogue for this col tile ----------------
            const int c0 = ((g >> 3) * NCTA_PER_ROW + j) * 128;
            size_t lvl_base; int lvl_stride, lvl_start;
            if (c0 < 1024)      { lvl_base = 0;                                         lvl_stride = 1024;  lvl_start = 0;    }
            else if (c0 < 5120) { lvl_base = (size_t)1024 * 1024;                       lvl_stride = 4096;  lvl_start = 1024; }
            else                { lvl_base = (size_t)1024 * 1024 + (size_t)4096 * 1024; lvl_stride = 16384; lvl_start = 5120; }

            #pragma unroll
            for (int mi = 0; mi < 4; mi++) {
                const int ra = r0 + m0 + mi * 16 + qr;
                const float xx0 = g_xx[ra];
                const float xx1 = g_xx[ra + 8];
                const float bb0 = 1.0f - CC * xx0;
                const float bb1 = 1.0f - CC * xx1;
                float* orow0 = out + lvl_base + (size_t)ra * lvl_stride + (c0 - lvl_start);
                float* orow1 = orow0 + (size_t)8 * lvl_stride;

                #pragma unroll
                for (int ni = 0; ni < 4; ni++) {
                    const int col = n0 + ni * 8 + qc;
                    const float2 yyp = *(const float2*)(g_yy + c0 + col);
                    float* a4 = acc[mi][ni];

                    float r[4];
                    #pragma unroll
                    for (int q = 0; q < 4; q++) {
                        const float xy = a4[q];
                        const float xx = (q < 2) ? xx0 : xx1;
                        const float bb = (q < 2) ? bb0 : bb1;
                        const float yv = (q & 1) ? yyp.y : yyp.x;
                        float w     = fmaf(-2.0f * CC, xy, 1.0f);
                        float a     = fmaf(CC, yv, w);
                        float denom = fmaf(CC * CC * xx, yv, w);
                        float num2  = a * a * xx + bb * bb * yv - 2.0f * a * bb * xy;
                        float s  = SQRTC * sqrtf(fmaxf(num2, 0.0f));
                        float td = fmaxf(fabsf(denom), 1e-30f);
                        s = fminf(s, (1.0f - EPSF) * td);
                        float ratio = __fdividef(td + s, td - s);
                        r[q] = KLOG2 * __log2f(ratio);
                        a4[q] = 0.0f;                     // reset acc for next tile
                    }
                    *(float2*)(orow0 + col) = make_float2(r[0], r[1]);
                    *(float2*)(orow1 + col) = make_float2(r[2], r[3]);
                }
            }
        }
    }
}

// =====================================================================
// launch
// =====================================================================
extern "C" void kernel_launch(void* const* d_in, const int* in_sizes, int n_in,
                              void* d_out, int out_size)
{
    const float* x     = (const float*)d_in[0];
    const float* W1    = (const float*)d_in[1];
    const float* b1    = (const float*)d_in[2];
    const float* W2    = (const float*)d_in[3];
    const float* b2    = (const float*)d_in[4];
    const float* W3    = (const float*)d_in[5];
    const float* b3    = (const float*)d_in[6];
    const float* proto = (const float*)d_in[7];
    float* out = (float*)d_out;

    float *p_h1, *p_h2, *p_f;
    cudaGetSymbolAddress((void**)&p_h1, g_h1);
    cudaGetSymbolAddress((void**)&p_h2, g_h2);
    cudaGetSymbolAddress((void**)&p_f,  g_f);

    cudaFuncSetAttribute(dist_mma, cudaFuncAttributeMaxDynamicSharedMemorySize, SM_BYTES);

    proto_kernel<<<PTOT / 8, 256>>>(proto);
    mlp_gemm<768, true ><<<dim3(4, 32), 128>>>(x,    W1, b1, p_h1);
    mlp_gemm<256, true ><<<dim3(4, 32), 128>>>(p_h1, W2, b2, p_h2);
    mlp_gemm<256, false><<<dim3(4, 32), 128>>>(p_h2, W3, b3, p_f);
    expmap_kernel<<<BDIM, 256>>>();
    dist_mma<<<8 * NCTA_PER_ROW, 256, SM_BYTES>>>(out);
}